// round 5
// baseline (speedup 1.0000x reference)
#include <cuda_runtime.h>
#include <math.h>

#define NEG_INF (__int_as_float(0xff800000))

// Problem constants
#define BB 4
#define SS 2048
#define EE 1024
#define AA 64

typedef unsigned long long u64;

// packed f32x2 helpers (ptxas never auto-emits FFMA2 from C++)
__device__ __forceinline__ u64 fma2(u64 a, u64 b, u64 c) {
    u64 d;
    asm("fma.rn.f32x2 %0, %1, %2, %3;" : "=l"(d) : "l"(a), "l"(b), "l"(c));
    return d;
}
__device__ __forceinline__ u64 pack2(float lo, float hi) {
    u64 r;
    asm("mov.b64 %0, {%1, %2};" : "=l"(r) : "f"(lo), "f"(hi));
    return r;
}
__device__ __forceinline__ float2 unpack2(u64 v) {
    float lo, hi;
    asm("mov.b64 {%0, %1}, %2;" : "=f"(lo), "=f"(hi) : "l"(v));
    return make_float2(lo, hi);
}
__device__ __forceinline__ float hsum2(u64 v) {
    float2 f = unpack2(v);
    return f.x + f.y;
}

// Scratch: K = emb @ Wk^T  [B, S, A] fp32 = 2 MB
__device__ float g_K[BB * SS * AA];

// ---------------------------------------------------------------------------
// Kernel 1: K projection.  C[r][a] = sum_e emb[r][e] * Wk[a][e]
// NT GEMM, packed f32x2 accumulation along the reduction dim.
// grid = 128 (64 rows each), block = 256 (16x16), 4x4 strided fragments.
// ---------------------------------------------------------------------------
__global__ __launch_bounds__(256, 2) void k_proj_kernel(
    const float* __restrict__ emb, const float* __restrict__ Wk)
{
    __shared__ float Es[64][68];   // row stride 272B = 17*16B -> float4 aligned
    __shared__ float Ws[64][68];

    const int t  = threadIdx.x;
    const int ty = t >> 4;
    const int tx = t & 15;
    const int rowbase = blockIdx.x * 64;

    u64 acc[4][4];
#pragma unroll
    for (int i = 0; i < 4; i++)
#pragma unroll
        for (int j = 0; j < 4; j++) acc[i][j] = 0ull;

    for (int et = 0; et < EE; et += 64) {
        __syncthreads();
#pragma unroll
        for (int g = 0; g < 4; g++) {
            int idx = t + g * 256;          // 1024 float4 slots = 64x64 floats
            int r  = idx >> 4;
            int c4 = idx & 15;
            *(float4*)&Es[r][c4 * 4] =
                *(const float4*)&emb[(rowbase + r) * EE + et + c4 * 4];
            *(float4*)&Ws[r][c4 * 4] =
                *(const float4*)&Wk[r * EE + et + c4 * 4];
        }
        __syncthreads();

#pragma unroll
        for (int e4 = 0; e4 < 16; e4++) {
            ulonglong2 a0 = *(const ulonglong2*)&Es[ty      ][e4 * 4];
            ulonglong2 a1 = *(const ulonglong2*)&Es[ty + 16][e4 * 4];
            ulonglong2 a2 = *(const ulonglong2*)&Es[ty + 32][e4 * 4];
            ulonglong2 a3 = *(const ulonglong2*)&Es[ty + 48][e4 * 4];
#pragma unroll
            for (int j = 0; j < 4; j++) {
                ulonglong2 b = *(const ulonglong2*)&Ws[tx + 16 * j][e4 * 4];
                acc[0][j] = fma2(a0.x, b.x, acc[0][j]);
                acc[0][j] = fma2(a0.y, b.y, acc[0][j]);
                acc[1][j] = fma2(a1.x, b.x, acc[1][j]);
                acc[1][j] = fma2(a1.y, b.y, acc[1][j]);
                acc[2][j] = fma2(a2.x, b.x, acc[2][j]);
                acc[2][j] = fma2(a2.y, b.y, acc[2][j]);
                acc[3][j] = fma2(a3.x, b.x, acc[3][j]);
                acc[3][j] = fma2(a3.y, b.y, acc[3][j]);
            }
        }
    }

#pragma unroll
    for (int i = 0; i < 4; i++) {
        int row = rowbase + ty + 16 * i;
#pragma unroll
        for (int j = 0; j < 4; j++)
            g_K[row * AA + tx + 16 * j] = hsum2(acc[i][j]);
    }
}

// ---------------------------------------------------------------------------
// Kernel 2: causal flash attention with q = k = v = g_K, packed f32x2 math.
// grid = 256 linear; bid -> (qt = 63 - bid/4, batch = bid%4) so the
// heaviest query tiles launch first (load balance across 148 SMs, 2 CTAs/SM).
// BQ=32 rows, BK=64 keys. Score fragment 2 rows x 4 keys; O fragment
// 2 rows x 4 dims.
// ---------------------------------------------------------------------------
__global__ __launch_bounds__(256, 2) void attn_kernel(float* __restrict__ out)
{
    __shared__ float Qs[32][68];
    __shared__ float Ks[64][68];   // serves as both K and V tile (v == k)
    __shared__ float Ps[32][68];

    const int t  = threadIdx.x;
    const int ty = t >> 4;
    const int tx = t & 15;
    const int bid = blockIdx.x;
    const int qt = 63 - (bid >> 2);       // heavy tiles first
    const int b  = bid & 3;
    const float* __restrict__ Kb = g_K + b * SS * AA;

    // load Q tile (32x64)
#pragma unroll
    for (int g = 0; g < 2; g++) {
        int idx = t + g * 256;            // 512 float4 = 32x64 floats
        int r  = idx >> 4;
        int c4 = idx & 15;
        *(float4*)&Qs[r][c4 * 4] =
            *(const float4*)&Kb[(qt * 32 + r) * 64 + c4 * 4];
    }

    u64 o0[2] = {0ull, 0ull};             // row ty     : dims tx*4..tx*4+3
    u64 o1[2] = {0ull, 0ull};             // row ty+16
    float m0 = NEG_INF, m1 = NEG_INF;
    float l0 = 0.f, l1 = 0.f;
    const int grow0 = qt * 32 + ty;
    const int grow1 = grow0 + 16;
    const int ktmax = (qt * 32 + 31) >> 6;   // inclusive

    for (int kt = 0; kt <= ktmax; kt++) {
        __syncthreads();    // prev iter's PV done reading Ks/Ps (also fences Qs)
#pragma unroll
        for (int g = 0; g < 4; g++) {
            int idx = t + g * 256;        // 1024 float4 = 64x64 floats
            int r  = idx >> 4;
            int c4 = idx & 15;
            *(float4*)&Ks[r][c4 * 4] =
                *(const float4*)&Kb[(kt * 64 + r) * 64 + c4 * 4];
        }
        __syncthreads();

        // ---- scores S = Q . K^T  (packed pairs along d) ----
        u64 a0[4] = {0ull, 0ull, 0ull, 0ull};
        u64 a1[4] = {0ull, 0ull, 0ull, 0ull};
#pragma unroll
        for (int d4 = 0; d4 < 16; d4++) {
            ulonglong2 q0 = *(const ulonglong2*)&Qs[ty     ][d4 * 4];
            ulonglong2 q1 = *(const ulonglong2*)&Qs[ty + 16][d4 * 4];
#pragma unroll
            for (int cc = 0; cc < 4; cc++) {
                ulonglong2 k = *(const ulonglong2*)&Ks[tx + 16 * cc][d4 * 4];
                a0[cc] = fma2(q0.x, k.x, a0[cc]);
                a0[cc] = fma2(q0.y, k.y, a0[cc]);
                a1[cc] = fma2(q1.x, k.x, a1[cc]);
                a1[cc] = fma2(q1.y, k.y, a1[cc]);
            }
        }

        // ---- scale + faithful mask: (col > row) OR (value == 0) ----
        float s0[4], s1[4];
#pragma unroll
        for (int cc = 0; cc < 4; cc++) {
            int gc = kt * 64 + tx + 16 * cc;
            float v0 = hsum2(a0[cc]) * 0.125f;
            float v1 = hsum2(a1[cc]) * 0.125f;
            s0[cc] = (gc > grow0 || v0 == 0.f) ? NEG_INF : v0;
            s1[cc] = (gc > grow1 || v1 == 0.f) ? NEG_INF : v1;
        }

        // ---- online softmax, row group 0 ----
        {
            float tm = fmaxf(fmaxf(s0[0], s0[1]), fmaxf(s0[2], s0[3]));
            tm = fmaxf(tm, __shfl_xor_sync(0xffffffffu, tm, 8));
            tm = fmaxf(tm, __shfl_xor_sync(0xffffffffu, tm, 4));
            tm = fmaxf(tm, __shfl_xor_sync(0xffffffffu, tm, 2));
            tm = fmaxf(tm, __shfl_xor_sync(0xffffffffu, tm, 1));
            float mn   = fmaxf(m0, tm);
            float corr = (m0 == mn) ? 1.f : __expf(m0 - mn);
            bool  dead = (mn == NEG_INF);
            float rs = 0.f;
#pragma unroll
            for (int cc = 0; cc < 4; cc++) {
                float p = dead ? 0.f : __expf(s0[cc] - mn);
                s0[cc] = p;
                rs += p;
            }
            rs += __shfl_xor_sync(0xffffffffu, rs, 8);
            rs += __shfl_xor_sync(0xffffffffu, rs, 4);
            rs += __shfl_xor_sync(0xffffffffu, rs, 2);
            rs += __shfl_xor_sync(0xffffffffu, rs, 1);
            l0 = l0 * corr + rs;
            m0 = mn;
            u64 c2 = pack2(corr, corr);
            o0[0] = fma2(o0[0], c2, 0ull);
            o0[1] = fma2(o0[1], c2, 0ull);
        }
        // ---- online softmax, row group 1 ----
        {
            float tm = fmaxf(fmaxf(s1[0], s1[1]), fmaxf(s1[2], s1[3]));
            tm = fmaxf(tm, __shfl_xor_sync(0xffffffffu, tm, 8));
            tm = fmaxf(tm, __shfl_xor_sync(0xffffffffu, tm, 4));
            tm = fmaxf(tm, __shfl_xor_sync(0xffffffffu, tm, 2));
            tm = fmaxf(tm, __shfl_xor_sync(0xffffffffu, tm, 1));
            float mn   = fmaxf(m1, tm);
            float corr = (m1 == mn) ? 1.f : __expf(m1 - mn);
            bool  dead = (mn == NEG_INF);
            float rs = 0.f;
#pragma unroll
            for (int cc = 0; cc < 4; cc++) {
                float p = dead ? 0.f : __expf(s1[cc] - mn);
                s1[cc] = p;
                rs += p;
            }
            rs += __shfl_xor_sync(0xffffffffu, rs, 8);
            rs += __shfl_xor_sync(0xffffffffu, rs, 4);
            rs += __shfl_xor_sync(0xffffffffu, rs, 2);
            rs += __shfl_xor_sync(0xffffffffu, rs, 1);
            l1 = l1 * corr + rs;
            m1 = mn;
            u64 c2 = pack2(corr, corr);
            o1[0] = fma2(o1[0], c2, 0ull);
            o1[1] = fma2(o1[1], c2, 0ull);
        }

        // ---- stage P in smem ----
#pragma unroll
        for (int cc = 0; cc < 4; cc++) {
            Ps[ty     ][tx + 16 * cc] = s0[cc];
            Ps[ty + 16][tx + 16 * cc] = s1[cc];
        }
        __syncthreads();

        // ---- O += P . V  (V tile == Ks), packed pairs along dim ----
#pragma unroll
        for (int k4 = 0; k4 < 16; k4++) {
            float4 p0 = *(const float4*)&Ps[ty     ][k4 * 4];
            float4 p1 = *(const float4*)&Ps[ty + 16][k4 * 4];
            const float* pp0 = (const float*)&p0;
            const float* pp1 = (const float*)&p1;
#pragma unroll
            for (int j = 0; j < 4; j++) {
                ulonglong2 v = *(const ulonglong2*)&Ks[k4 * 4 + j][tx * 4];
                u64 b0 = pack2(pp0[j], pp0[j]);
                u64 b1 = pack2(pp1[j], pp1[j]);
                o0[0] = fma2(b0, v.x, o0[0]);
                o0[1] = fma2(b0, v.y, o0[1]);
                o1[0] = fma2(b1, v.x, o1[0]);
                o1[1] = fma2(b1, v.y, o1[1]);
            }
        }
    }

    // ---- epilogue: normalize + store ----
    float inv0 = 1.f / l0;
    float inv1 = 1.f / l1;
    float2 r00 = unpack2(o0[0]), r01 = unpack2(o0[1]);
    float2 r10 = unpack2(o1[0]), r11 = unpack2(o1[1]);
    float4 w0 = make_float4(r00.x * inv0, r00.y * inv0, r01.x * inv0, r01.y * inv0);
    float4 w1 = make_float4(r10.x * inv1, r10.y * inv1, r11.x * inv1, r11.y * inv1);

    int row0 = b * SS + qt * 32 + ty;
    *(float4*)&out[(row0     ) * 64 + tx * 4] = w0;
    *(float4*)&out[(row0 + 16) * 64 + tx * 4] = w1;
}

// ---------------------------------------------------------------------------
extern "C" void kernel_launch(void* const* d_in, const int* in_sizes, int n_in,
                              void* d_out, int out_size)
{
    const float* emb = (const float*)d_in[0];   // [4, 2048, 1024]
    const float* Wk  = (const float*)d_in[1];   // [64, 1024]
    float* out = (float*)d_out;                 // [4, 2048, 64]
    (void)in_sizes; (void)n_in; (void)out_size;

    k_proj_kernel<<<128, 256>>>(emb, Wk);
    attn_kernel<<<256, 256>>>(out);
}

// round 7
// speedup vs baseline: 1.3240x; 1.3240x over previous
#include <cuda_runtime.h>
#include <math.h>

#define NEG_INF (__int_as_float(0xff800000))

// Problem constants
#define BB 4
#define SS 2048
#define EE 1024
#define AA 64

typedef unsigned long long u64;

// packed f32x2 helpers (ptxas never auto-emits FFMA2 from C++)
__device__ __forceinline__ u64 fma2(u64 a, u64 b, u64 c) {
    u64 d;
    asm("fma.rn.f32x2 %0, %1, %2, %3;" : "=l"(d) : "l"(a), "l"(b), "l"(c));
    return d;
}
__device__ __forceinline__ float2 unpack2(u64 v) {
    float lo, hi;
    asm("mov.b64 {%0, %1}, %2;" : "=f"(lo), "=f"(hi) : "l"(v));
    return make_float2(lo, hi);
}
__device__ __forceinline__ float hsum2(u64 v) {
    float2 f = unpack2(v);
    return f.x + f.y;
}

// Scratch: K = emb @ Wk^T  [B, S, A] fp32 = 2 MB
__device__ float g_K[BB * SS * AA];

// ---------------------------------------------------------------------------
// Kernel 1: K projection (FFMA2 version — measured ~11 us in R5, keep).
// ---------------------------------------------------------------------------
__global__ __launch_bounds__(256, 2) void k_proj_kernel(
    const float* __restrict__ emb, const float* __restrict__ Wk)
{
    __shared__ float Es[64][68];
    __shared__ float Ws[64][68];

    const int t  = threadIdx.x;
    const int ty = t >> 4;
    const int tx = t & 15;
    const int rowbase = blockIdx.x * 64;

    u64 acc[4][4];
#pragma unroll
    for (int i = 0; i < 4; i++)
#pragma unroll
        for (int j = 0; j < 4; j++) acc[i][j] = 0ull;

    for (int et = 0; et < EE; et += 64) {
        __syncthreads();
#pragma unroll
        for (int g = 0; g < 4; g++) {
            int idx = t + g * 256;
            int r  = idx >> 4;
            int c4 = idx & 15;
            *(float4*)&Es[r][c4 * 4] =
                *(const float4*)&emb[(rowbase + r) * EE + et + c4 * 4];
            *(float4*)&Ws[r][c4 * 4] =
                *(const float4*)&Wk[r * EE + et + c4 * 4];
        }
        __syncthreads();

#pragma unroll
        for (int e4 = 0; e4 < 16; e4++) {
            ulonglong2 a0 = *(const ulonglong2*)&Es[ty      ][e4 * 4];
            ulonglong2 a1 = *(const ulonglong2*)&Es[ty + 16][e4 * 4];
            ulonglong2 a2 = *(const ulonglong2*)&Es[ty + 32][e4 * 4];
            ulonglong2 a3 = *(const ulonglong2*)&Es[ty + 48][e4 * 4];
#pragma unroll
            for (int j = 0; j < 4; j++) {
                ulonglong2 b = *(const ulonglong2*)&Ws[tx + 16 * j][e4 * 4];
                acc[0][j] = fma2(a0.x, b.x, acc[0][j]);
                acc[0][j] = fma2(a0.y, b.y, acc[0][j]);
                acc[1][j] = fma2(a1.x, b.x, acc[1][j]);
                acc[1][j] = fma2(a1.y, b.y, acc[1][j]);
                acc[2][j] = fma2(a2.x, b.x, acc[2][j]);
                acc[2][j] = fma2(a2.y, b.y, acc[2][j]);
                acc[3][j] = fma2(a3.x, b.x, acc[3][j]);
                acc[3][j] = fma2(a3.y, b.y, acc[3][j]);
            }
        }
    }

#pragma unroll
    for (int i = 0; i < 4; i++) {
        int row = rowbase + ty + 16 * i;
#pragma unroll
        for (int j = 0; j < 4; j++)
            g_K[row * AA + tx + 16 * j] = hsum2(acc[i][j]);
    }
}

// ---------------------------------------------------------------------------
// Kernel 2: causal flash attention, q = k = v = g_K.  SCALAR FFMA (crossbar-
// bound; FFMA2 was a measured regression here).
// BQ=32, BK=128, 4x4 fragments. 256 threads: ty = warpid (0..7), tx = lane.
// Score frag: rows ty+8i (i<4), keys tx+32j (j<4).
// PV: dims (tx&15)*4, key-halves interleaved by chunks of 4 (h = tx>>4),
// merged with one shfl_xor(16) per float at the end (corr factors are
// warp-uniform so linearity holds).
// grid = 128 (32 pairs x 4 batches), pair (p, 63-p) => equal ~18 iters/block.
// Dynamic smem: Qs[32][68] + Ks[128][68] + Ps[32][132] = 60416 B.
// ---------------------------------------------------------------------------
#define QS_STRIDE 68
#define KS_STRIDE 68
#define PS_STRIDE 132
#define QS_OFF 0
#define KS_OFF (32 * QS_STRIDE)                 // 2176
#define PS_OFF (KS_OFF + 128 * KS_STRIDE)       // 10880
#define ATTN_SMEM_BYTES ((PS_OFF + 32 * PS_STRIDE) * 4)   // 60416

__global__ __launch_bounds__(256, 1) void attn_kernel(float* __restrict__ out)
{
    extern __shared__ float sm[];
    float* Qs = sm + QS_OFF;
    float* Ks = sm + KS_OFF;
    float* Ps = sm + PS_OFF;

    const int t  = threadIdx.x;
    const int ty = t >> 5;          // warp id, uniform per warp
    const int tx = t & 31;          // lane
    const int dtx = tx & 15;        // PV dim group
    const int h   = tx >> 4;        // PV key-half selector
    const int bid = blockIdx.x;
    const int p = bid >> 2;
    const int b = bid & 3;
    const float* __restrict__ Kb = g_K + b * SS * AA;

    for (int half = 0; half < 2; half++) {
        const int qt = half ? (63 - p) : p;

        __syncthreads();            // smem reuse across halves
        // load Q tile (32 x 64)
#pragma unroll
        for (int g = 0; g < 2; g++) {
            int idx = t + g * 256;
            int r  = idx >> 4;
            int c4 = idx & 15;
            *(float4*)&Qs[r * QS_STRIDE + c4 * 4] =
                *(const float4*)&Kb[(qt * 32 + r) * 64 + c4 * 4];
        }

        float4 o[4];
        float  m[4], l[4];
#pragma unroll
        for (int i = 0; i < 4; i++) {
            o[i] = make_float4(0.f, 0.f, 0.f, 0.f);
            m[i] = NEG_INF;
            l[i] = 0.f;
        }
        const int rowg = qt * 32 + ty;              // + 8i per fragment row
        const int ktmax = (qt * 32 + 31) >> 7;      // inclusive, BK=128

        for (int kt = 0; kt <= ktmax; kt++) {
            __syncthreads();        // prev PV done reading Ks/Ps
            // load K tile (128 x 64)
#pragma unroll
            for (int g = 0; g < 8; g++) {
                int idx = t + g * 256;
                int r  = idx >> 4;
                int c4 = idx & 15;
                *(float4*)&Ks[r * KS_STRIDE + c4 * 4] =
                    *(const float4*)&Kb[(kt * 128 + r) * 64 + c4 * 4];
            }
            __syncthreads();

            // ---- scores: 4 rows x 4 keys per thread ----
            float s[4][4];
#pragma unroll
            for (int i = 0; i < 4; i++)
#pragma unroll
                for (int j = 0; j < 4; j++) s[i][j] = 0.f;

#pragma unroll
            for (int d4 = 0; d4 < 16; d4++) {
                float4 q[4], k[4];
#pragma unroll
                for (int i = 0; i < 4; i++)
                    q[i] = *(const float4*)&Qs[(ty + 8 * i) * QS_STRIDE + d4 * 4];
#pragma unroll
                for (int j = 0; j < 4; j++)
                    k[j] = *(const float4*)&Ks[(tx + 32 * j) * KS_STRIDE + d4 * 4];
#pragma unroll
                for (int i = 0; i < 4; i++)
#pragma unroll
                    for (int j = 0; j < 4; j++)
                        s[i][j] += q[i].x * k[j].x + q[i].y * k[j].y
                                 + q[i].z * k[j].z + q[i].w * k[j].w;
            }

            // ---- scale + faithful mask: (col > row) OR (value == 0) ----
#pragma unroll
            for (int j = 0; j < 4; j++) {
                int gc = kt * 128 + tx + 32 * j;
#pragma unroll
                for (int i = 0; i < 4; i++) {
                    float v = s[i][j] * 0.125f;
                    s[i][j] = (gc > rowg + 8 * i || v == 0.f) ? NEG_INF : v;
                }
            }

            // ---- online softmax per fragment row (warp-wide reduce) ----
#pragma unroll
            for (int i = 0; i < 4; i++) {
                float tm = fmaxf(fmaxf(s[i][0], s[i][1]), fmaxf(s[i][2], s[i][3]));
                tm = fmaxf(tm, __shfl_xor_sync(0xffffffffu, tm, 16));
                tm = fmaxf(tm, __shfl_xor_sync(0xffffffffu, tm, 8));
                tm = fmaxf(tm, __shfl_xor_sync(0xffffffffu, tm, 4));
                tm = fmaxf(tm, __shfl_xor_sync(0xffffffffu, tm, 2));
                tm = fmaxf(tm, __shfl_xor_sync(0xffffffffu, tm, 1));
                float mn   = fmaxf(m[i], tm);
                float corr = (m[i] == mn) ? 1.f : __expf(m[i] - mn);
                bool  dead = (mn == NEG_INF);
                float rs = 0.f;
#pragma unroll
                for (int j = 0; j < 4; j++) {
                    float pv = dead ? 0.f : __expf(s[i][j] - mn);
                    s[i][j] = pv;
                    rs += pv;
                }
                rs += __shfl_xor_sync(0xffffffffu, rs, 16);
                rs += __shfl_xor_sync(0xffffffffu, rs, 8);
                rs += __shfl_xor_sync(0xffffffffu, rs, 4);
                rs += __shfl_xor_sync(0xffffffffu, rs, 2);
                rs += __shfl_xor_sync(0xffffffffu, rs, 1);
                l[i] = l[i] * corr + rs;
                m[i] = mn;
                o[i].x *= corr; o[i].y *= corr; o[i].z *= corr; o[i].w *= corr;
            }

            // ---- stage P ----
#pragma unroll
            for (int i = 0; i < 4; i++)
#pragma unroll
                for (int j = 0; j < 4; j++)
                    Ps[(ty + 8 * i) * PS_STRIDE + tx + 32 * j] = s[i][j];
            __syncthreads();

            // ---- O += P . V  (V tile == Ks), interleaved key-halves ----
#pragma unroll
            for (int c = 0; c < 16; c++) {
                int kb = c * 8 + h * 4;     // this lane's key chunk
                float4 p4[4];
#pragma unroll
                for (int i = 0; i < 4; i++)
                    p4[i] = *(const float4*)&Ps[(ty + 8 * i) * PS_STRIDE + kb];
#pragma unroll
                for (int j = 0; j < 4; j++) {
                    float4 v = *(const float4*)&Ks[(kb + j) * KS_STRIDE + dtx * 4];
                    const float* pp[4] = {(const float*)&p4[0], (const float*)&p4[1],
                                          (const float*)&p4[2], (const float*)&p4[3]};
#pragma unroll
                    for (int i = 0; i < 4; i++) {
                        float a = pp[i][j];
                        o[i].x += a * v.x; o[i].y += a * v.y;
                        o[i].z += a * v.z; o[i].w += a * v.w;
                    }
                }
            }
        }

        // ---- merge key-halves (corr history is warp-uniform => linear) ----
#pragma unroll
        for (int i = 0; i < 4; i++) {
            o[i].x += __shfl_xor_sync(0xffffffffu, o[i].x, 16);
            o[i].y += __shfl_xor_sync(0xffffffffu, o[i].y, 16);
            o[i].z += __shfl_xor_sync(0xffffffffu, o[i].z, 16);
            o[i].w += __shfl_xor_sync(0xffffffffu, o[i].w, 16);
        }

        // ---- epilogue: normalize + store (half the lanes) ----
        if (h == 0) {
#pragma unroll
            for (int i = 0; i < 4; i++) {
                float inv = 1.f / l[i];
                float4 w = make_float4(o[i].x * inv, o[i].y * inv,
                                       o[i].z * inv, o[i].w * inv);
                int row = b * SS + qt * 32 + ty + 8 * i;
                *(float4*)&out[row * 64 + dtx * 4] = w;
            }
        }
    }
}

// ---------------------------------------------------------------------------
extern "C" void kernel_launch(void* const* d_in, const int* in_sizes, int n_in,
                              void* d_out, int out_size)
{
    const float* emb = (const float*)d_in[0];   // [4, 2048, 1024]
    const float* Wk  = (const float*)d_in[1];   // [64, 1024]
    float* out = (float*)d_out;                 // [4, 2048, 64]
    (void)in_sizes; (void)n_in; (void)out_size;

    cudaFuncSetAttribute(attn_kernel,
                         cudaFuncAttributeMaxDynamicSharedMemorySize,
                         ATTN_SMEM_BYTES);

    k_proj_kernel<<<128, 256>>>(emb, Wk);
    attn_kernel<<<128, 256, ATTN_SMEM_BYTES>>>(out);
}

// round 8
// speedup vs baseline: 1.3871x; 1.0476x over previous
#include <cuda_runtime.h>
#include <math.h>

#define NEG_INF (__int_as_float(0xff800000))

// Problem constants
#define BB 4
#define SS 2048
#define EE 1024
#define AA 64

typedef unsigned long long u64;

// packed f32x2 helpers (ptxas never auto-emits FFMA2 from C++)
__device__ __forceinline__ u64 fma2(u64 a, u64 b, u64 c) {
    u64 d;
    asm("fma.rn.f32x2 %0, %1, %2, %3;" : "=l"(d) : "l"(a), "l"(b), "l"(c));
    return d;
}
__device__ __forceinline__ float2 unpack2(u64 v) {
    float lo, hi;
    asm("mov.b64 {%0, %1}, %2;" : "=f"(lo), "=f"(hi) : "l"(v));
    return make_float2(lo, hi);
}
__device__ __forceinline__ float hsum2(u64 v) {
    float2 f = unpack2(v);
    return f.x + f.y;
}

// Scratch: K = emb @ Wk^T  [B, S, A] fp32 = 2 MB
__device__ float g_K[BB * SS * AA];

// ---------------------------------------------------------------------------
// Kernel 1: K projection (FFMA2 version — measured ~11 us, keep).
// ---------------------------------------------------------------------------
__global__ __launch_bounds__(256, 2) void k_proj_kernel(
    const float* __restrict__ emb, const float* __restrict__ Wk)
{
    __shared__ float Es[64][68];
    __shared__ float Ws[64][68];

    const int t  = threadIdx.x;
    const int ty = t >> 4;
    const int tx = t & 15;
    const int rowbase = blockIdx.x * 64;

    u64 acc[4][4];
#pragma unroll
    for (int i = 0; i < 4; i++)
#pragma unroll
        for (int j = 0; j < 4; j++) acc[i][j] = 0ull;

    for (int et = 0; et < EE; et += 64) {
        __syncthreads();
#pragma unroll
        for (int g = 0; g < 4; g++) {
            int idx = t + g * 256;
            int r  = idx >> 4;
            int c4 = idx & 15;
            *(float4*)&Es[r][c4 * 4] =
                *(const float4*)&emb[(rowbase + r) * EE + et + c4 * 4];
            *(float4*)&Ws[r][c4 * 4] =
                *(const float4*)&Wk[r * EE + et + c4 * 4];
        }
        __syncthreads();

#pragma unroll
        for (int e4 = 0; e4 < 16; e4++) {
            ulonglong2 a0 = *(const ulonglong2*)&Es[ty      ][e4 * 4];
            ulonglong2 a1 = *(const ulonglong2*)&Es[ty + 16][e4 * 4];
            ulonglong2 a2 = *(const ulonglong2*)&Es[ty + 32][e4 * 4];
            ulonglong2 a3 = *(const ulonglong2*)&Es[ty + 48][e4 * 4];
#pragma unroll
            for (int j = 0; j < 4; j++) {
                ulonglong2 b = *(const ulonglong2*)&Ws[tx + 16 * j][e4 * 4];
                acc[0][j] = fma2(a0.x, b.x, acc[0][j]);
                acc[0][j] = fma2(a0.y, b.y, acc[0][j]);
                acc[1][j] = fma2(a1.x, b.x, acc[1][j]);
                acc[1][j] = fma2(a1.y, b.y, acc[1][j]);
                acc[2][j] = fma2(a2.x, b.x, acc[2][j]);
                acc[2][j] = fma2(a2.y, b.y, acc[2][j]);
                acc[3][j] = fma2(a3.x, b.x, acc[3][j]);
                acc[3][j] = fma2(a3.y, b.y, acc[3][j]);
            }
        }
    }

#pragma unroll
    for (int i = 0; i < 4; i++) {
        int row = rowbase + ty + 16 * i;
#pragma unroll
        for (int j = 0; j < 4; j++)
            g_K[row * AA + tx + 16 * j] = hsum2(acc[i][j]);
    }
}

// ---------------------------------------------------------------------------
// Kernel 2: causal flash attention, q = k = v = g_K.  Scalar FFMA.
// CTA = 128 threads (4 warps), BQ=16, BK=128 => 2 CTAs/SM co-resident
// (smem 47.6KB, regs fit), so barrier/memory stalls of one CTA overlap
// with the other's compute.
// Score frag: rows ty+4i (i<4, ty=warp 0..3), keys tx+32j (j<4).
// PV: dims (tx&15)*4, key-halves interleaved in chunks of 4 (h = tx>>4),
// merged with shfl_xor(16) at the end (corr factors warp-uniform).
// grid = 512 = 128 q-tiles x 4 batches, heaviest q-tiles launched first.
// Dynamic smem: Qs[16][68] + Ks[128][68] + Ps[16][132] = 47.5 KB.
// ---------------------------------------------------------------------------
#define QS_STRIDE 68
#define KS_STRIDE 68
#define PS_STRIDE 132
#define QS_OFF 0
#define KS_OFF (16 * QS_STRIDE)                 // 1088
#define PS_OFF (KS_OFF + 128 * KS_STRIDE)       // 9792
#define ATTN_SMEM_BYTES ((PS_OFF + 16 * PS_STRIDE) * 4)   // 47616

__global__ __launch_bounds__(128, 2) void attn_kernel(float* __restrict__ out)
{
    extern __shared__ float sm[];
    float* Qs = sm + QS_OFF;
    float* Ks = sm + KS_OFF;
    float* Ps = sm + PS_OFF;

    const int t  = threadIdx.x;
    const int ty = t >> 5;          // warp id 0..3
    const int tx = t & 31;          // lane
    const int dtx = tx & 15;        // PV dim group
    const int h   = tx >> 4;        // PV key-half selector
    const int bid = blockIdx.x;
    const int qt2 = 127 - (bid >> 2);   // heavy tiles first
    const int b   = bid & 3;
    const float* __restrict__ Kb = g_K + b * SS * AA;

    // load Q tile (16 x 64): 256 float4, 128 threads -> 2 each
#pragma unroll
    for (int g = 0; g < 2; g++) {
        int idx = t + g * 128;
        int r  = idx >> 4;
        int c4 = idx & 15;
        *(float4*)&Qs[r * QS_STRIDE + c4 * 4] =
            *(const float4*)&Kb[(qt2 * 16 + r) * 64 + c4 * 4];
    }

    float4 o[4];
    float  m[4], l[4];
#pragma unroll
    for (int i = 0; i < 4; i++) {
        o[i] = make_float4(0.f, 0.f, 0.f, 0.f);
        m[i] = NEG_INF;
        l[i] = 0.f;
    }
    const int rowg = qt2 * 16 + ty;             // + 4i per fragment row
    const int ktmax = (qt2 * 16 + 15) >> 7;     // inclusive, BK=128

    for (int kt = 0; kt <= ktmax; kt++) {
        __syncthreads();        // prev PV done reading Ks/Ps (also fences Qs)
        // load K tile (128 x 64): 2048 float4, 128 threads -> 16 each
#pragma unroll
        for (int g = 0; g < 16; g++) {
            int idx = t + g * 128;
            int r  = idx >> 4;
            int c4 = idx & 15;
            *(float4*)&Ks[r * KS_STRIDE + c4 * 4] =
                *(const float4*)&Kb[(kt * 128 + r) * 64 + c4 * 4];
        }
        __syncthreads();

        // ---- scores: 4 rows x 4 keys per thread ----
        float s[4][4];
#pragma unroll
        for (int i = 0; i < 4; i++)
#pragma unroll
            for (int j = 0; j < 4; j++) s[i][j] = 0.f;

#pragma unroll
        for (int d4 = 0; d4 < 16; d4++) {
            float4 q[4], k[4];
#pragma unroll
            for (int i = 0; i < 4; i++)
                q[i] = *(const float4*)&Qs[(ty + 4 * i) * QS_STRIDE + d4 * 4];
#pragma unroll
            for (int j = 0; j < 4; j++)
                k[j] = *(const float4*)&Ks[(tx + 32 * j) * KS_STRIDE + d4 * 4];
#pragma unroll
            for (int i = 0; i < 4; i++)
#pragma unroll
                for (int j = 0; j < 4; j++)
                    s[i][j] += q[i].x * k[j].x + q[i].y * k[j].y
                             + q[i].z * k[j].z + q[i].w * k[j].w;
        }

        // ---- scale + faithful mask: (col > row) OR (value == 0) ----
#pragma unroll
        for (int j = 0; j < 4; j++) {
            int gc = kt * 128 + tx + 32 * j;
#pragma unroll
            for (int i = 0; i < 4; i++) {
                float v = s[i][j] * 0.125f;
                s[i][j] = (gc > rowg + 4 * i || v == 0.f) ? NEG_INF : v;
            }
        }

        // ---- online softmax per fragment row (warp-wide reduce) ----
#pragma unroll
        for (int i = 0; i < 4; i++) {
            float tm = fmaxf(fmaxf(s[i][0], s[i][1]), fmaxf(s[i][2], s[i][3]));
            tm = fmaxf(tm, __shfl_xor_sync(0xffffffffu, tm, 16));
            tm = fmaxf(tm, __shfl_xor_sync(0xffffffffu, tm, 8));
            tm = fmaxf(tm, __shfl_xor_sync(0xffffffffu, tm, 4));
            tm = fmaxf(tm, __shfl_xor_sync(0xffffffffu, tm, 2));
            tm = fmaxf(tm, __shfl_xor_sync(0xffffffffu, tm, 1));
            float mn   = fmaxf(m[i], tm);
            float corr = (m[i] == mn) ? 1.f : __expf(m[i] - mn);
            bool  dead = (mn == NEG_INF);
            float rs = 0.f;
#pragma unroll
            for (int j = 0; j < 4; j++) {
                float pv = dead ? 0.f : __expf(s[i][j] - mn);
                s[i][j] = pv;
                rs += pv;
            }
            rs += __shfl_xor_sync(0xffffffffu, rs, 16);
            rs += __shfl_xor_sync(0xffffffffu, rs, 8);
            rs += __shfl_xor_sync(0xffffffffu, rs, 4);
            rs += __shfl_xor_sync(0xffffffffu, rs, 2);
            rs += __shfl_xor_sync(0xffffffffu, rs, 1);
            l[i] = l[i] * corr + rs;
            m[i] = mn;
            o[i].x *= corr; o[i].y *= corr; o[i].z *= corr; o[i].w *= corr;
        }

        // ---- stage P ----
#pragma unroll
        for (int i = 0; i < 4; i++)
#pragma unroll
            for (int j = 0; j < 4; j++)
                Ps[(ty + 4 * i) * PS_STRIDE + tx + 32 * j] = s[i][j];
        __syncthreads();

        // ---- O += P . V  (V tile == Ks), interleaved key-halves ----
#pragma unroll
        for (int c = 0; c < 16; c++) {
            int kb = c * 8 + h * 4;     // this lane's key chunk
            float4 p4[4];
#pragma unroll
            for (int i = 0; i < 4; i++)
                p4[i] = *(const float4*)&Ps[(ty + 4 * i) * PS_STRIDE + kb];
#pragma unroll
            for (int j = 0; j < 4; j++) {
                float4 v = *(const float4*)&Ks[(kb + j) * KS_STRIDE + dtx * 4];
                const float* pp[4] = {(const float*)&p4[0], (const float*)&p4[1],
                                      (const float*)&p4[2], (const float*)&p4[3]};
#pragma unroll
                for (int i = 0; i < 4; i++) {
                    float a = pp[i][j];
                    o[i].x += a * v.x; o[i].y += a * v.y;
                    o[i].z += a * v.z; o[i].w += a * v.w;
                }
            }
        }
    }

    // ---- merge key-halves (corr history is warp-uniform => linear) ----
#pragma unroll
    for (int i = 0; i < 4; i++) {
        o[i].x += __shfl_xor_sync(0xffffffffu, o[i].x, 16);
        o[i].y += __shfl_xor_sync(0xffffffffu, o[i].y, 16);
        o[i].z += __shfl_xor_sync(0xffffffffu, o[i].z, 16);
        o[i].w += __shfl_xor_sync(0xffffffffu, o[i].w, 16);
    }

    // ---- epilogue: normalize + store (half the lanes) ----
    if (h == 0) {
#pragma unroll
        for (int i = 0; i < 4; i++) {
            float inv = 1.f / l[i];
            float4 w = make_float4(o[i].x * inv, o[i].y * inv,
                                   o[i].z * inv, o[i].w * inv);
            int row = b * SS + qt2 * 16 + ty + 4 * i;
            *(float4*)&out[row * 64 + dtx * 4] = w;
        }
    }
}

// ---------------------------------------------------------------------------
extern "C" void kernel_launch(void* const* d_in, const int* in_sizes, int n_in,
                              void* d_out, int out_size)
{
    const float* emb = (const float*)d_in[0];   // [4, 2048, 1024]
    const float* Wk  = (const float*)d_in[1];   // [64, 1024]
    float* out = (float*)d_out;                 // [4, 2048, 64]
    (void)in_sizes; (void)n_in; (void)out_size;

    cudaFuncSetAttribute(attn_kernel,
                         cudaFuncAttributeMaxDynamicSharedMemorySize,
                         ATTN_SMEM_BYTES);

    k_proj_kernel<<<128, 256>>>(emb, Wk);
    attn_kernel<<<512, 128, ATTN_SMEM_BYTES>>>(out);
}

// round 14
// speedup vs baseline: 1.6080x; 1.1592x over previous
#include <cuda_runtime.h>
#include <cstdint>
#include <math.h>

#define NEG_INF (__int_as_float(0xff800000))

// Problem constants
#define BB 4
#define SS 2048
#define EE 1024
#define AA 64

typedef unsigned long long u64;
typedef unsigned int u32;

// packed f32x2 helpers (ptxas never auto-emits FFMA2 from C++)
__device__ __forceinline__ u64 fma2(u64 a, u64 b, u64 c) {
    u64 d;
    asm("fma.rn.f32x2 %0, %1, %2, %3;" : "=l"(d) : "l"(a), "l"(b), "l"(c));
    return d;
}
__device__ __forceinline__ float2 unpack2(u64 v) {
    float lo, hi;
    asm("mov.b64 {%0, %1}, %2;" : "=f"(lo), "=f"(hi) : "l"(v));
    return make_float2(lo, hi);
}
__device__ __forceinline__ float hsum2(u64 v) {
    float2 f = unpack2(v);
    return f.x + f.y;
}

// cp.async 16B (LDGSTS) helpers
__device__ __forceinline__ void cp_async16(u32 smem_addr, const void* gptr) {
    asm volatile("cp.async.cg.shared.global [%0], [%1], 16;"
                 :: "r"(smem_addr), "l"(gptr) : "memory");
}
__device__ __forceinline__ void cp_async_commit() {
    asm volatile("cp.async.commit_group;" ::: "memory");
}
__device__ __forceinline__ void cp_async_wait0() {
    asm volatile("cp.async.wait_group 0;" ::: "memory");
}
__device__ __forceinline__ u32 smem_u32(const void* p) {
    u32 a;
    asm("{ .reg .u64 t; cvta.to.shared.u64 t, %1; cvt.u32.u64 %0, t; }"
        : "=r"(a) : "l"(p));
    return a;
}

// Scratch: K = emb @ Wk^T  [B, S, A] fp32 = 2 MB
__device__ float g_K[BB * SS * AA];

// ---------------------------------------------------------------------------
// Kernel 1: K projection (FFMA2 version — measured ~11 us, keep).
// ---------------------------------------------------------------------------
__global__ __launch_bounds__(256, 2) void k_proj_kernel(
    const float* __restrict__ emb, const float* __restrict__ Wk)
{
    __shared__ float Es[64][68];
    __shared__ float Ws[64][68];

    const int t  = threadIdx.x;
    const int ty = t >> 4;
    const int tx = t & 15;
    const int rowbase = blockIdx.x * 64;

    u64 acc[4][4];
#pragma unroll
    for (int i = 0; i < 4; i++)
#pragma unroll
        for (int j = 0; j < 4; j++) acc[i][j] = 0ull;

    for (int et = 0; et < EE; et += 64) {
        __syncthreads();
#pragma unroll
        for (int g = 0; g < 4; g++) {
            int idx = t + g * 256;
            int r  = idx >> 4;
            int c4 = idx & 15;
            *(float4*)&Es[r][c4 * 4] =
                *(const float4*)&emb[(rowbase + r) * EE + et + c4 * 4];
            *(float4*)&Ws[r][c4 * 4] =
                *(const float4*)&Wk[r * EE + et + c4 * 4];
        }
        __syncthreads();

#pragma unroll
        for (int e4 = 0; e4 < 16; e4++) {
            ulonglong2 a0 = *(const ulonglong2*)&Es[ty      ][e4 * 4];
            ulonglong2 a1 = *(const ulonglong2*)&Es[ty + 16][e4 * 4];
            ulonglong2 a2 = *(const ulonglong2*)&Es[ty + 32][e4 * 4];
            ulonglong2 a3 = *(const ulonglong2*)&Es[ty + 48][e4 * 4];
#pragma unroll
            for (int j = 0; j < 4; j++) {
                ulonglong2 b = *(const ulonglong2*)&Ws[tx + 16 * j][e4 * 4];
                acc[0][j] = fma2(a0.x, b.x, acc[0][j]);
                acc[0][j] = fma2(a0.y, b.y, acc[0][j]);
                acc[1][j] = fma2(a1.x, b.x, acc[1][j]);
                acc[1][j] = fma2(a1.y, b.y, acc[1][j]);
                acc[2][j] = fma2(a2.x, b.x, acc[2][j]);
                acc[2][j] = fma2(a2.y, b.y, acc[2][j]);
                acc[3][j] = fma2(a3.x, b.x, acc[3][j]);
                acc[3][j] = fma2(a3.y, b.y, acc[3][j]);
            }
        }
    }

#pragma unroll
    for (int i = 0; i < 4; i++) {
        int row = rowbase + ty + 16 * i;
#pragma unroll
        for (int j = 0; j < 4; j++)
            g_K[row * AA + tx + 16 * j] = hsum2(acc[i][j]);
    }
}

// ---------------------------------------------------------------------------
// Kernel 2: causal flash attention, q = k = v = g_K.
// CTA = 128 threads (4 warps), BQ=16, BK=128, 2 CTAs/SM.
//  - K tiles double-buffered via cp.async (LDGSTS). Copy scheme (FIXED):
//    each thread owns column-group lc4 = t&15 and rows lr + 8g (lr = t>>4,
//    g < 16)  ->  128 rows x 16 groups covered exactly once.
//  - ONE __syncthreads per iter; P staging warp-local -> __syncwarp.
//  - QK inner loop packed fma.rn.f32x2; PV scalar.
// Dynamic smem: Qs[16][68] + 2*Ks[128][68] + Ps[16][132] = 82432 B.
// ---------------------------------------------------------------------------
#define QS_STRIDE 68
#define KS_STRIDE 68
#define PS_STRIDE 132
#define QS_OFF 0
#define KS0_OFF (16 * QS_STRIDE)                    // 1088
#define KS_TILE (128 * KS_STRIDE)                   // 8704
#define PS_OFF (KS0_OFF + 2 * KS_TILE)              // 18496
#define ATTN_SMEM_BYTES ((PS_OFF + 16 * PS_STRIDE) * 4)   // 82432

__global__ __launch_bounds__(128, 2) void attn_kernel(float* __restrict__ out)
{
    extern __shared__ float sm[];
    float* Qs = sm + QS_OFF;
    float* Ps = sm + PS_OFF;

    const int t  = threadIdx.x;
    const int ty = t >> 5;          // warp id 0..3
    const int tx = t & 31;          // lane
    const int dtx = tx & 15;        // PV dim group
    const int h   = tx >> 4;        // PV key-half selector
    const int bid = blockIdx.x;
    const int qt2 = 127 - (bid >> 2);   // heavy tiles first
    const int b   = bid & 3;
    const float* __restrict__ Kb = g_K + b * SS * AA;

    const int ktmax = (qt2 * 16 + 15) >> 7;     // inclusive, BK=128

    // per-thread cp.async slot: rows lr + 8g (g<16), column group lc4
    const int lr  = t >> 4;         // 0..7
    const int lc4 = t & 15;         // 16B column group

    // ---- prefetch K tile 0 into buffer 0 ----
    {
        u32 dst = smem_u32(sm + KS0_OFF) + (u32)((lr * KS_STRIDE + lc4 * 4) * 4);
        const float* src = Kb + lr * 64 + lc4 * 4;
#pragma unroll
        for (int g = 0; g < 16; g++)
            cp_async16(dst + g * 8 * KS_STRIDE * 4, src + g * 8 * 64);
        cp_async_commit();
    }

    // ---- load Q tile (16 x 64): 256 float4, 128 threads -> 2 each ----
#pragma unroll
    for (int g = 0; g < 2; g++) {
        int idx = t + g * 128;
        int r  = idx >> 4;
        int c4 = idx & 15;
        *(float4*)&Qs[r * QS_STRIDE + c4 * 4] =
            *(const float4*)&Kb[(qt2 * 16 + r) * 64 + c4 * 4];
    }

    float4 o[4];
    float  m[4], l[4];
#pragma unroll
    for (int i = 0; i < 4; i++) {
        o[i] = make_float4(0.f, 0.f, 0.f, 0.f);
        m[i] = NEG_INF;
        l[i] = 0.f;
    }
    const int rowg = qt2 * 16 + ty;             // + 4i per fragment row

    for (int kt = 0; kt <= ktmax; kt++) {
        float* Ks = sm + KS0_OFF + (kt & 1) * KS_TILE;

        cp_async_wait0();       // my copies for tile kt done
        __syncthreads();        // everyone's copies visible; prev compute done

        // ---- prefetch tile kt+1 into the other buffer ----
        if (kt < ktmax) {
            u32 dst = smem_u32(sm + KS0_OFF + ((kt + 1) & 1) * KS_TILE)
                    + (u32)((lr * KS_STRIDE + lc4 * 4) * 4);
            const float* src = Kb + ((kt + 1) * 128 + lr) * 64 + lc4 * 4;
#pragma unroll
            for (int g = 0; g < 16; g++)
                cp_async16(dst + g * 8 * KS_STRIDE * 4, src + g * 8 * 64);
            cp_async_commit();
        }

        // ---- scores: 4 rows x 4 keys, packed f32x2 along d ----
        u64 s2[4][4];
#pragma unroll
        for (int i = 0; i < 4; i++)
#pragma unroll
            for (int j = 0; j < 4; j++) s2[i][j] = 0ull;

#pragma unroll
        for (int d4 = 0; d4 < 16; d4++) {
            ulonglong2 q2[4], k2[4];
#pragma unroll
            for (int i = 0; i < 4; i++)
                q2[i] = *(const ulonglong2*)&Qs[(ty + 4 * i) * QS_STRIDE + d4 * 4];
#pragma unroll
            for (int j = 0; j < 4; j++)
                k2[j] = *(const ulonglong2*)&Ks[(tx + 32 * j) * KS_STRIDE + d4 * 4];
#pragma unroll
            for (int i = 0; i < 4; i++)
#pragma unroll
                for (int j = 0; j < 4; j++) {
                    s2[i][j] = fma2(q2[i].x, k2[j].x, s2[i][j]);
                    s2[i][j] = fma2(q2[i].y, k2[j].y, s2[i][j]);
                }
        }

        // ---- reduce pairs + scale + faithful mask ----
        float s[4][4];
#pragma unroll
        for (int j = 0; j < 4; j++) {
            int gc = kt * 128 + tx + 32 * j;
#pragma unroll
            for (int i = 0; i < 4; i++) {
                float v = hsum2(s2[i][j]) * 0.125f;
                s[i][j] = (gc > rowg + 4 * i || v == 0.f) ? NEG_INF : v;
            }
        }

        // ---- online softmax per fragment row (warp-wide reduce) ----
#pragma unroll
        for (int i = 0; i < 4; i++) {
            float tm = fmaxf(fmaxf(s[i][0], s[i][1]), fmaxf(s[i][2], s[i][3]));
            tm = fmaxf(tm, __shfl_xor_sync(0xffffffffu, tm, 16));
            tm = fmaxf(tm, __shfl_xor_sync(0xffffffffu, tm, 8));
            tm = fmaxf(tm, __shfl_xor_sync(0xffffffffu, tm, 4));
            tm = fmaxf(tm, __shfl_xor_sync(0xffffffffu, tm, 2));
            tm = fmaxf(tm, __shfl_xor_sync(0xffffffffu, tm, 1));
            float mn   = fmaxf(m[i], tm);
            float corr = (m[i] == mn) ? 1.f : __expf(m[i] - mn);
            bool  dead = (mn == NEG_INF);
            float rs = 0.f;
#pragma unroll
            for (int j = 0; j < 4; j++) {
                float pv = dead ? 0.f : __expf(s[i][j] - mn);
                s[i][j] = pv;
                rs += pv;
            }
            rs += __shfl_xor_sync(0xffffffffu, rs, 16);
            rs += __shfl_xor_sync(0xffffffffu, rs, 8);
            rs += __shfl_xor_sync(0xffffffffu, rs, 4);
            rs += __shfl_xor_sync(0xffffffffu, rs, 2);
            rs += __shfl_xor_sync(0xffffffffu, rs, 1);
            l[i] = l[i] * corr + rs;
            m[i] = mn;
            o[i].x *= corr; o[i].y *= corr; o[i].z *= corr; o[i].w *= corr;
        }

        // ---- stage P (warp-local: warp ty owns rows ty+4i) ----
#pragma unroll
        for (int i = 0; i < 4; i++)
#pragma unroll
            for (int j = 0; j < 4; j++)
                Ps[(ty + 4 * i) * PS_STRIDE + tx + 32 * j] = s[i][j];
        __syncwarp();

        // ---- O += P . V  (V tile == Ks), interleaved key-halves ----
#pragma unroll
        for (int c = 0; c < 16; c++) {
            int kb = c * 8 + h * 4;     // this lane's key chunk
            float4 p4[4];
#pragma unroll
            for (int i = 0; i < 4; i++)
                p4[i] = *(const float4*)&Ps[(ty + 4 * i) * PS_STRIDE + kb];
#pragma unroll
            for (int j = 0; j < 4; j++) {
                float4 v = *(const float4*)&Ks[(kb + j) * KS_STRIDE + dtx * 4];
                const float* pp[4] = {(const float*)&p4[0], (const float*)&p4[1],
                                      (const float*)&p4[2], (const float*)&p4[3]};
#pragma unroll
                for (int i = 0; i < 4; i++) {
                    float a = pp[i][j];
                    o[i].x += a * v.x; o[i].y += a * v.y;
                    o[i].z += a * v.z; o[i].w += a * v.w;
                }
            }
        }
    }

    // ---- merge key-halves (corr history is warp-uniform => linear) ----
#pragma unroll
    for (int i = 0; i < 4; i++) {
        o[i].x += __shfl_xor_sync(0xffffffffu, o[i].x, 16);
        o[i].y += __shfl_xor_sync(0xffffffffu, o[i].y, 16);
        o[i].z += __shfl_xor_sync(0xffffffffu, o[i].z, 16);
        o[i].w += __shfl_xor_sync(0xffffffffu, o[i].w, 16);
    }

    // ---- epilogue: normalize + store (half the lanes) ----
    if (h == 0) {
#pragma unroll
        for (int i = 0; i < 4; i++) {
            float inv = 1.f / l[i];
            float4 w = make_float4(o[i].x * inv, o[i].y * inv,
                                   o[i].z * inv, o[i].w * inv);
            int row = b * SS + qt2 * 16 + ty + 4 * i;
            *(float4*)&out[row * 64 + dtx * 4] = w;
        }
    }
}

// ---------------------------------------------------------------------------
extern "C" void kernel_launch(void* const* d_in, const int* in_sizes, int n_in,
                              void* d_out, int out_size)
{
    const float* emb = (const float*)d_in[0];   // [4, 2048, 1024]
    const float* Wk  = (const float*)d_in[1];   // [64, 1024]
    float* out = (float*)d_out;                 // [4, 2048, 64]
    (void)in_sizes; (void)n_in; (void)out_size;

    cudaFuncSetAttribute(attn_kernel,
                         cudaFuncAttributeMaxDynamicSharedMemorySize,
                         ATTN_SMEM_BYTES);

    k_proj_kernel<<<128, 256>>>(emb, Wk);
    attn_kernel<<<512, 128, ATTN_SMEM_BYTES>>>(out);
}